// round 15
// baseline (speedup 1.0000x reference)
#include <cuda_runtime.h>
#include <cuda_bf16.h>
#include <math.h>
#include <stdint.h>

#define B_    16
#define T_    1000
#define INDIM 257
#define FEAT  771
#define H_    512
#define KN    9
#define KS    6
#define M_    (B_*T_)        /* 16000 rows, time-major: row = t*B + b */
#define H3    (3*H_)         /* 1536 */
#define A2K   (H_*KN)        /* 4608 */
#define KP1   832            /* padded K for input GEMM (771 -> 832, /64) */
#define PLANE ((size_t)M_*H_)

/* tc_gemm tiling */
#define MT 128
#define NT 128
#define KC 64                /* K chunk: 64 bf16 per 128B smem row */

/* tc_gemm smem layout (single buffer) */
#define S_TM   0
#define S_MB   8
#define S_AH   1024
#define S_AL   (S_AH + 16384)
#define S_BH   (S_AL + 16384)
#define S_BL   (S_BH + 16384)
#define S_TOT  (S_BL + 16384)

#if defined(__CUDA_ARCH_FEAT_SM103_ALL) || defined(__CUDA_ARCH_FEAT_SM100_ALL)
#define HAS_TCGEN05 1
#endif

typedef __nv_bfloat16 bf16;

/* ---------------- scratch (device globals; no allocation allowed) -------- */
__device__ __align__(16) bf16 g_xTh[(size_t)M_*KP1];
__device__ __align__(16) bf16 g_xTl[(size_t)M_*KP1];
__device__ __align__(16) bf16 g_h0h[(size_t)M_*H_];
__device__ __align__(16) bf16 g_h0l[(size_t)M_*H_];
__device__ float g_U  [(size_t)M_*H3];
__device__ __align__(16) bf16 g_h1h[(size_t)M_*H_];
__device__ __align__(16) bf16 g_h1l[(size_t)M_*H_];
__device__ __align__(16) bf16 g_h2h[(size_t)M_*H_];
__device__ __align__(16) bf16 g_h2l[(size_t)M_*H_];
__device__ __align__(16) bf16 g_A2h[(size_t)M_*A2K];
__device__ __align__(16) bf16 g_A2l[(size_t)M_*A2K];
__device__ __align__(16) bf16 g_Wih[(size_t)H_*KP1];     // W_in^T  [512][832]
__device__ __align__(16) bf16 g_Wil[(size_t)H_*KP1];
__device__ __align__(16) bf16 g_Wr0h[(size_t)H3*H_];     // W_rnn0^T [1536][512]
__device__ __align__(16) bf16 g_Wr0l[(size_t)H3*H_];
__device__ __align__(16) bf16 g_Wr1h[(size_t)H3*H_];
__device__ __align__(16) bf16 g_Wr1l[(size_t)H3*H_];
__device__ __align__(16) bf16 g_Woh[(size_t)384*A2K];    // W_out slice^T (rows>=257 zero)
__device__ __align__(16) bf16 g_Wol[(size_t)384*A2K];

/* ---------------- generic helpers (legal on all targets) ----------------- */
__device__ __forceinline__ void bsplit(float x, bf16 &h, bf16 &l) {
    h = __float2bfloat16_rn(x);
    l = __float2bfloat16_rn(x - __bfloat162float(h));
}
__device__ __forceinline__ float brecon(bf16 h, bf16 l) {
    return __bfloat162float(h) + __bfloat162float(l);
}

#ifdef HAS_TCGEN05
__device__ __forceinline__ uint32_t smem_u32(const void* p) {
    uint32_t a;
    asm("{ .reg .u64 t; cvta.to.shared.u64 t, %1; cvt.u32.u64 %0, t; }" : "=r"(a) : "l"(p));
    return a;
}
__device__ __forceinline__ uint32_t elect1() {
    uint32_t p;
    asm volatile("{ .reg .pred p; elect.sync _|p, 0xFFFFFFFF; selp.b32 %0, 1, 0, p; }" : "=r"(p));
    return p;
}
__device__ __forceinline__ void mbar_init(uint32_t a, uint32_t c) {
    asm volatile("mbarrier.init.shared.b64 [%0], %1;" :: "r"(a), "r"(c) : "memory");
}
__device__ __forceinline__ void mbar_inval(uint32_t a) {
    asm volatile("mbarrier.inval.shared.b64 [%0];" :: "r"(a) : "memory");
}
__device__ __forceinline__ void mbar_wait(uint32_t a, uint32_t ph) {
    asm volatile(
        "{\n\t.reg .pred P;\n\t"
        "LW%=:\n\t"
        "mbarrier.try_wait.parity.acquire.cta.shared::cta.b64 P, [%0], %1, 0x989680;\n\t"
        "@P bra LD%=;\n\t"
        "bra LW%=;\n\t"
        "LD%=:\n\t}"
        :: "r"(a), "r"(ph) : "memory");
}
__device__ __forceinline__ void tm_alloc(uint32_t smem_dst, uint32_t ncols) {
    asm volatile("tcgen05.alloc.cta_group::1.sync.aligned.shared::cta.b32 [%0], %1;"
                 :: "r"(smem_dst), "r"(ncols) : "memory");
}
__device__ __forceinline__ void tm_relinq() {
    asm volatile("tcgen05.relinquish_alloc_permit.cta_group::1.sync.aligned;");
}
__device__ __forceinline__ void tm_dealloc(uint32_t tm, uint32_t ncols) {
    asm volatile("tcgen05.dealloc.cta_group::1.sync.aligned.b32 %0, %1;" :: "r"(tm), "r"(ncols));
}
__device__ __forceinline__ void tm_commit(uint32_t mbar) {
    asm volatile("tcgen05.commit.cta_group::1.mbarrier::arrive::one.shared::cluster.b64 [%0];"
                 :: "r"(mbar) : "memory");
}
__device__ __forceinline__ void fence_after() {
    asm volatile("tcgen05.fence::after_thread_sync;" ::: "memory");
}
__device__ __forceinline__ void fence_async_shared() {
    asm volatile("fence.proxy.async.shared::cta;" ::: "memory");
}
__device__ __forceinline__ void mma_bf16_ss(uint32_t d, uint64_t a, uint64_t b,
                                            uint32_t idesc, bool en) {
    uint32_t e = en ? 1u : 0u;
    asm volatile(
        "{\n\t.reg .pred p;\n\t"
        "setp.ne.u32 p, %5, 0;\n\t"
        "tcgen05.mma.cta_group::1.kind::f16 [%0], %1, %2, %3, {%4, %4, %4, %4}, p;\n\t}"
        :: "r"(d), "l"(a), "l"(b), "r"(idesc), "r"(0u), "r"(e) : "memory");
}
#define LDTM_X32(r, addr) \
    asm volatile( \
        "tcgen05.ld.sync.aligned.32x32b.x32.b32 " \
        "{%0,%1,%2,%3,%4,%5,%6,%7,%8,%9,%10,%11,%12,%13,%14,%15," \
        "%16,%17,%18,%19,%20,%21,%22,%23,%24,%25,%26,%27,%28,%29,%30,%31}, [%32];" \
        : "=r"((r)[0]),"=r"((r)[1]),"=r"((r)[2]),"=r"((r)[3]), \
          "=r"((r)[4]),"=r"((r)[5]),"=r"((r)[6]),"=r"((r)[7]), \
          "=r"((r)[8]),"=r"((r)[9]),"=r"((r)[10]),"=r"((r)[11]), \
          "=r"((r)[12]),"=r"((r)[13]),"=r"((r)[14]),"=r"((r)[15]), \
          "=r"((r)[16]),"=r"((r)[17]),"=r"((r)[18]),"=r"((r)[19]), \
          "=r"((r)[20]),"=r"((r)[21]),"=r"((r)[22]),"=r"((r)[23]), \
          "=r"((r)[24]),"=r"((r)[25]),"=r"((r)[26]),"=r"((r)[27]), \
          "=r"((r)[28]),"=r"((r)[29]),"=r"((r)[30]),"=r"((r)[31]) \
        : "r"(addr))
__device__ __forceinline__ void wait_ld() {
    asm volatile("tcgen05.wait::ld.sync.aligned;" ::: "memory");
}
__device__ __forceinline__ uint64_t mk_desc(uint32_t addr) {
    return ((uint64_t)2 << 61) | ((uint64_t)1 << 46) | ((uint64_t)64 << 32)
         | ((uint64_t)1 << 16) | (((uint64_t)addr >> 4) & 0x3FFF);
}
#endif /* HAS_TCGEN05 */

/* ---------------- transpose (b,t,f)->(t,b,f), bf16 split, K-pad ---------- */
__global__ void transpose_kernel(const float* __restrict__ in,
                                 bf16* __restrict__ xh, bf16* __restrict__ xl) {
    int row = blockIdx.x;                  // t*B + b
    int t = row >> 4, b = row & 15;
    const float* src = in + ((size_t)b*T_ + t)*FEAT;
    bf16* dh = xh + (size_t)row*KP1;
    bf16* dl = xl + (size_t)row*KP1;
    for (int f = threadIdx.x; f < KP1; f += blockDim.x) {
        float v = (f < FEAT) ? src[f] : 0.f;
        bf16 h, l; bsplit(v, h, l);
        dh[f] = h; dl[f] = l;
    }
}

/* ---------------- fused weight prep (ONE launch): transpose+split+pad ---- */
__global__ void wprep_all(const float* __restrict__ Wi, const float* __restrict__ Wr,
                          const float* __restrict__ Wo,
                          bf16* __restrict__ Wih, bf16* __restrict__ Wil,
                          bf16* __restrict__ Wr0h, bf16* __restrict__ Wr0l,
                          bf16* __restrict__ Wr1h, bf16* __restrict__ Wr1l,
                          bf16* __restrict__ Woh, bf16* __restrict__ Wol)
{
    int bid = blockIdx.x;
    const float* W; int srcld, n0, ncols, K, Kpad; bf16 *dh, *dl; int n;
    if (bid < 512) {
        n = bid; W = Wi; srcld = H_; n0 = 0; ncols = H_; K = FEAT; Kpad = KP1;
        dh = Wih + (size_t)n*Kpad; dl = Wil + (size_t)n*Kpad;
    } else if (bid < 2048) {
        n = bid - 512; W = Wr; srcld = H3; n0 = 0; ncols = H3; K = H_; Kpad = H_;
        dh = Wr0h + (size_t)n*Kpad; dl = Wr0l + (size_t)n*Kpad;
    } else if (bid < 3584) {
        n = bid - 2048; W = Wr + (size_t)H_*H3; srcld = H3; n0 = 0; ncols = H3; K = H_; Kpad = H_;
        dh = Wr1h + (size_t)n*Kpad; dl = Wr1l + (size_t)n*Kpad;
    } else {
        n = bid - 3584; W = Wo; srcld = FEAT; n0 = INDIM; ncols = INDIM; K = A2K; Kpad = A2K;
        dh = Woh + (size_t)n*Kpad; dl = Wol + (size_t)n*Kpad;
    }
    bool nv = (n < ncols);
    for (int k = threadIdx.x; k < Kpad; k += blockDim.x) {
        float v = (nv && k < K) ? W[(size_t)k*srcld + n0 + n] : 0.f;
        bf16 h, l; bsplit(v, h, l);
        dh[k] = h; dl[k] = l;
    }
}

/* ---------------- GEMM 128x128 tile, bf16 2-split, register prefetch ------
 * C[M,N] = (Ah+Al)[M,K] @ (Bh+Bl)^T  with Bt stored [N][K] (bf16 planes).
 * Products kept: AhBh + AlBh + AhBl (err ~2^-18 rel).
 * Single smem buffer; next chunk's LDGs issued right after the current
 * chunk's MMA dispatch so load latency hides under the MMA chain.
 * Epilogue stages 32x32 tiles via padded smem so stores are coalesced rows.
 * EPI 0: C = acc (ldc)
 * EPI 1: t = tanh(acc + bias[n]); Chi/Clo = bsplit(t)   (ldc)
 * EPI 2: out[row,n] = sigmoid(acc+bias[n]) * inp[row, 257+n], n < N(=257)
 */
template<int EPI>
__global__ __launch_bounds__(128)
void tc_gemm(const bf16* __restrict__ Ahi, const bf16* __restrict__ Alo, int lda,
             const bf16* __restrict__ Bhi, const bf16* __restrict__ Blo, int ldb,
             float* __restrict__ C, bf16* __restrict__ Chi, bf16* __restrict__ Clo,
             int ldc, int N, int K,
             const float* __restrict__ bias,
             const float* __restrict__ inp, float* __restrict__ outp)
{
    extern __shared__ char smem[];
    int tid = threadIdx.x;
    int mBase = blockIdx.y * MT, nBase = blockIdx.x * NT;

#ifdef HAS_TCGEN05
    uint32_t sb = smem_u32(smem);
    int wid = tid >> 5, lane = tid & 31;

    if (wid == 0) { tm_alloc(sb + S_TM, 128); tm_relinq(); }
    if (tid == 0) mbar_init(sb + S_MB, 1);
    __syncthreads();
    uint32_t tmem;
    asm volatile("ld.shared.b32 %0, [%1];" : "=r"(tmem) : "r"(sb + S_TM));

    /* kind::f16 bf16 idesc: dtype=F32(1<<4), atype=BF16(1<<7), btype=BF16(1<<10) */
    const uint32_t idesc = (1u << 4) | (1u << 7) | (1u << 10)
                         | ((NT / 8) << 17) | ((MT / 16) << 24);
    uint64_t adh = mk_desc(sb + S_AH), adl = mk_desc(sb + S_AL);
    uint64_t bdh = mk_desc(sb + S_BH), bdl = mk_desc(sb + S_BL);

    /* per-thread row/col mapping: idx=j*128+tid; 8 lanes cover one 128B row */
    int swoj[8]; size_t oAj[8], oBj[8];
    #pragma unroll
    for (int j = 0; j < 8; j++) {
        int idx = j*128 + tid;
        int r = idx >> 3, c = idx & 7;
        oAj[j] = (size_t)(mBase + r)*lda + c*8;
        oBj[j] = (size_t)(nBase + r)*ldb + c*8;
        swoj[j] = (int)(((uint32_t)(r*128 + c*16)) ^ (((uint32_t)(r & 7)) << 4));
    }

    float4 rA0[8], rA1[8], rB0[8], rB1[8];
    /* prologue: prefetch chunk 0 */
    #pragma unroll
    for (int j = 0; j < 8; j++) {
        rA0[j] = *reinterpret_cast<const float4*>(Ahi + oAj[j]);
        rA1[j] = *reinterpret_cast<const float4*>(Alo + oAj[j]);
        rB0[j] = *reinterpret_cast<const float4*>(Bhi + oBj[j]);
        rB1[j] = *reinterpret_cast<const float4*>(Blo + oBj[j]);
    }

    int nch = K / KC;
    uint32_t ph = 0;
    for (int ch = 0; ch < nch; ch++) {
        if (ch > 0) { mbar_wait(sb + S_MB, ph); ph ^= 1; }
        #pragma unroll
        for (int j = 0; j < 8; j++) {
            *reinterpret_cast<float4*>(smem + S_AH + swoj[j]) = rA0[j];
            *reinterpret_cast<float4*>(smem + S_AL + swoj[j]) = rA1[j];
            *reinterpret_cast<float4*>(smem + S_BH + swoj[j]) = rB0[j];
            *reinterpret_cast<float4*>(smem + S_BL + swoj[j]) = rB1[j];
        }
        fence_async_shared();
        __syncthreads();
        if (wid == 0 && elect1()) {
            #pragma unroll
            for (int ks = 0; ks < 4; ks++) {          // k-step = 16 bf16 = 32B = +2 units
                uint64_t off = (uint64_t)(ks * 2);
                mma_bf16_ss(tmem, adh + off, bdh + off, idesc, !(ch == 0 && ks == 0));
                mma_bf16_ss(tmem, adl + off, bdh + off, idesc, true);
                mma_bf16_ss(tmem, adh + off, bdl + off, idesc, true);
            }
            tm_commit(sb + S_MB);
        }
        /* prefetch next chunk while MMAs run; next wait hides the latency */
        if (ch + 1 < nch) {
            int k1 = (ch + 1) * KC;
            #pragma unroll
            for (int j = 0; j < 8; j++) {
                rA0[j] = *reinterpret_cast<const float4*>(Ahi + oAj[j] + k1);
                rA1[j] = *reinterpret_cast<const float4*>(Alo + oAj[j] + k1);
                rB0[j] = *reinterpret_cast<const float4*>(Bhi + oBj[j] + k1);
                rB1[j] = *reinterpret_cast<const float4*>(Blo + oBj[j] + k1);
            }
        }
    }
    mbar_wait(sb + S_MB, (uint32_t)((nch - 1) & 1));
    fence_after();

    /* epilogue: warp w owns rows m0..m0+31; columns in 4 groups of 32.
       EPI0/1: stage 32x32 via padded smem (mainloop tiles now free) so
       global stores are coalesced full rows. */
    int m0 = mBase + wid*32;
    int m = m0 + lane;
    float* stg = reinterpret_cast<float*>(smem + S_AH) + wid*(32*33);
    #pragma unroll
    for (int cb = 0; cb < 4; cb++) {
        uint32_t d[32];
        LDTM_X32(d, tmem + cb*32);
        wait_ld();
        int nb = nBase + cb*32;
        if (EPI == 2) {
            int b = m & 15, t = m >> 4;
            size_t row = (size_t)b*T_ + t;
            #pragma unroll
            for (int c = 0; c < 32; c++) {
                int n = nb + c;
                if (n < N) {
                    float v = __uint_as_float(d[c]) + bias[n];
                    float s = 1.f / (1.f + __expf(-v));
                    outp[row*INDIM + n] = s * inp[row*FEAT + INDIM + n];
                }
            }
        } else {
            #pragma unroll
            for (int c = 0; c < 32; c++) stg[c*33 + lane] = __uint_as_float(d[c]);
            __syncwarp();
            if (EPI == 0) {
                int n = nb + lane;
                #pragma unroll 8
                for (int rr = 0; rr < 32; rr++)
                    C[(size_t)(m0+rr)*ldc + n] = stg[lane*33 + rr];
            } else {
                int n = nb + lane;
                float bn = bias[n];
                #pragma unroll 8
                for (int rr = 0; rr < 32; rr++) {
                    float t = tanhf(stg[lane*33 + rr] + bn);
                    bf16 h, l; bsplit(t, h, l);
                    Chi[(size_t)(m0+rr)*ldc + n] = h;
                    Clo[(size_t)(m0+rr)*ldc + n] = l;
                }
            }
            __syncwarp();
        }
    }

    __syncthreads();
    if (tid == 0) mbar_inval(sb + S_MB);
    __syncthreads();
    if (wid == 0) tm_dealloc(tmem, 128);

#else  /* ---------- SIMT FFMA fallback (non sm_103a targets) ------------- */
    float* As = reinterpret_cast<float*>(smem);            // [128][33]
    float* Bs = reinterpret_cast<float*>(smem + 17408);    // [128][33]
    const bf16* arh = Ahi + (size_t)(mBase + tid)*lda;
    const bf16* arl = Alo + (size_t)(mBase + tid)*lda;
    const bf16* brh = Bhi + (size_t)(nBase + tid)*ldb;
    const bf16* brl = Blo + (size_t)(nBase + tid)*ldb;

    for (int half = 0; half < 2; half++) {
        float acc[64];
        #pragma unroll
        for (int j = 0; j < 64; j++) acc[j] = 0.f;
        for (int k0 = 0; k0 < K; k0 += 32) {
            for (int q = 0; q < 32; q++) {
                As[tid*33 + q] = brecon(arh[k0+q], arl[k0+q]);
                Bs[tid*33 + q] = brecon(brh[k0+q], brl[k0+q]);
            }
            __syncthreads();
            for (int kk = 0; kk < 32; kk++) {
                float a = As[tid*33 + kk];
                #pragma unroll
                for (int j = 0; j < 64; j++)
                    acc[j] = fmaf(a, Bs[(half*64 + j)*33 + kk], acc[j]);
            }
            __syncthreads();
        }
        int m = mBase + tid;
        int nb = nBase + half*64;
        if (EPI == 0) {
            float* dst = C + (size_t)m*ldc + nb;
            for (int j = 0; j < 64; j++) dst[j] = acc[j];
        } else if (EPI == 1) {
            for (int j = 0; j < 64; j++) {
                int n = nb + j;
                float t = tanhf(acc[j] + bias[n]);
                bf16 h, l; bsplit(t, h, l);
                Chi[(size_t)m*ldc + n] = h;
                Clo[(size_t)m*ldc + n] = l;
            }
        } else {
            int b = m & 15, t = m >> 4;
            size_t row = (size_t)b*T_ + t;
            for (int j = 0; j < 64; j++) {
                int n = nb + j;
                if (n < N) {
                    float v = acc[j] + bias[n];
                    float s = 1.f / (1.f + __expf(-v));
                    outp[row*INDIM + n] = s * inp[row*FEAT + INDIM + n];
                }
            }
        }
    }
#endif
}

/* ---------------- SRU scan: bf16 X in, bf16 H out, pipelined -------------
 * Launched as 256 blocks x 32 threads to spread across all SMs. */
#define SUN 8
__global__ void scan_kernel(const float* __restrict__ U,
                            const bf16* __restrict__ Xh, const bf16* __restrict__ Xl,
                            const float* __restrict__ v, const float* __restrict__ bb,
                            bf16* __restrict__ Hh, bf16* __restrict__ Hl)
{
    int idx = blockIdx.x * blockDim.x + threadIdx.x;   // 0..B*H-1
    int b = idx >> 9, h = idx & (H_-1);
    float vf = v[h], vr = v[H_ + h];
    float bf = bb[h], br = bb[H_ + h];
    const float* Ub  = U  + (size_t)b*H3 + h;
    const bf16* Xhb = Xh + (size_t)b*H_ + h;
    const bf16* Xlb = Xl + (size_t)b*H_ + h;
    bf16* Hhb = Hh + (size_t)b*H_ + h;
    bf16* Hlb = Hl + (size_t)b*H_ + h;

    float cxt[SUN], cfp[SUN], crp[SUN], cxn[SUN];
    #pragma unroll
    for (int u = 0; u < SUN; u++) {
        size_t o3 = (size_t)u * (B_*H3);
        size_t o1 = (size_t)u * (B_*H_);
        cxt[u] = Ub[o3]; cfp[u] = Ub[o3 + H_]; crp[u] = Ub[o3 + 2*H_];
        cxn[u] = brecon(Xhb[o1], Xlb[o1]);
    }
    float c = 0.f;
    for (int t0 = 0; t0 < T_; t0 += SUN) {
        float nxt[SUN], nfp[SUN], nrp[SUN], nxn[SUN];
        bool more = (t0 + SUN < T_);
        #pragma unroll
        for (int u = 0; u < SUN; u++) {
            int t = t0 + SUN + u;
            size_t o3 = (size_t)t * (B_*H3);
            size_t o1 = (size_t)t * (B_*H_);
            if (more) {
                nxt[u] = Ub[o3]; nfp[u] = Ub[o3 + H_]; nrp[u] = Ub[o3 + 2*H_];
                nxn[u] = brecon(Xhb[o1], Xlb[o1]);
            } else { nxt[u] = nfp[u] = nrp[u] = nxn[u] = 0.f; }
        }
        #pragma unroll
        for (int u = 0; u < SUN; u++) {
            float f = 1.f / (1.f + __expf(-(fmaf(vf, c, cfp[u]) + bf)));
            float cn = fmaf(f, c - cxt[u], cxt[u]);
            float r = 1.f / (1.f + __expf(-(fmaf(vr, c, crp[u]) + br)));
            float hv = fmaf(r, cn - cxn[u], cxn[u]);
            bf16 hh, hl; bsplit(hv, hh, hl);
            size_t o1 = (size_t)(t0+u) * (B_*H_);
            Hhb[o1] = hh; Hlb[o1] = hl;
            c = cn;
        }
        #pragma unroll
        for (int u = 0; u < SUN; u++) {
            cxt[u] = nxt[u]; cfp[u] = nfp[u]; crp[u] = nrp[u]; cxn[u] = nxn[u];
        }
    }
}

/* ---------------- fused conv6x6 + maxpool3x3 + tanh, bf16 split output --- */
__global__ __launch_bounds__(256)
void convpool_kernel(const float* __restrict__ w, const float* __restrict__ cb,
                     const bf16* __restrict__ inh, const bf16* __restrict__ inl,
                     bf16* __restrict__ A2h, bf16* __restrict__ A2l)
{
    __shared__ float ws[KN][KS][KS];
    __shared__ float bs[KN];
    __shared__ float xin[15][40];
    __shared__ float cv[KN][10][36];
    __shared__ float po[8][32*KN];

    int b  = blockIdx.z;
    int t0 = blockIdx.y * 8;
    int h0 = blockIdx.x * 32;
    int tid = threadIdx.x;

    for (int i = tid; i < KN*KS*KS; i += 256) (&ws[0][0][0])[i] = w[i];
    if (tid < KN) bs[tid] = cb[tid];
    for (int i = tid; i < 15*39; i += 256) {
        int r = i / 39, cc = i % 39;
        int t = t0 - 4 + r, h = h0 - 4 + cc;
        float val = 0.f;
        if (t >= 0 && t < T_ && h >= 0 && h < H_) {
            size_t o = ((size_t)t*B_ + b)*H_ + h;
            val = brecon(inh[o], inl[o]);
        }
        xin[r][cc] = val;
    }
    __syncthreads();

    for (int p = tid; p < 10*34; p += 256) {
        int r = p / 34, cc = p % 34;
        int tt = t0 - 1 + r, hh = h0 - 1 + cc;
        float acc[KN];
        #pragma unroll
        for (int kn = 0; kn < KN; kn++) acc[kn] = 0.f;
        #pragma unroll
        for (int i = 0; i < KS; i++)
            #pragma unroll
            for (int j = 0; j < KS; j++) {
                float x = xin[r + i][cc + j];
                #pragma unroll
                for (int kn = 0; kn < KN; kn++)
                    acc[kn] = fmaf(ws[kn][i][j], x, acc[kn]);
            }
        bool valid = (tt >= 0 && tt < T_ && hh >= 0 && hh < H_);
        #pragma unroll
        for (int kn = 0; kn < KN; kn++)
            cv[kn][r][cc] = valid ? acc[kn] : -3.0e38f;
    }
    __syncthreads();

    {
        int ht = tid & 31, tt = tid >> 5;
        #pragma unroll
        for (int kn = 0; kn < KN; kn++) {
            float m = -3.0e38f;
            #pragma unroll
            for (int dt = 0; dt < 3; dt++)
                #pragma unroll
                for (int dh = 0; dh < 3; dh++)
                    m = fmaxf(m, cv[kn][tt + dt][ht + dh]);
            po[tt][ht*KN + kn] = tanhf(m + bs[kn]);
        }
    }
    __syncthreads();

    for (int i = tid; i < 8*32*KN; i += 256) {
        int row = i / (32*KN), f = i % (32*KN);
        size_t o = ((size_t)(t0 + row)*B_ + b)*A2K + (size_t)h0*KN + f;
        bf16 h, l; bsplit(po[row][f], h, l);
        A2h[o] = h; A2l[o] = l;
    }
}

/* ---------------- driver -------------------------------------------------- */
extern "C" void kernel_launch(void* const* d_in, const int* in_sizes, int n_in,
                              void* d_out, int out_size)
{
    const float* inputs = (const float*)d_in[0];
    const float* W_in   = (const float*)d_in[1];
    const float* b_in   = (const float*)d_in[2];
    const float* W_rnn  = (const float*)d_in[3];
    const float* v_rnn  = (const float*)d_in[4];
    const float* b_rnn  = (const float*)d_in[5];
    const float* conv_k = (const float*)d_in[6];
    const float* conv_b = (const float*)d_in[7];
    const float* W_out  = (const float*)d_in[8];
    const float* b_out  = (const float*)d_in[9];
    float* out = (float*)d_out;

    bf16 *xTh,*xTl,*h0h,*h0l,*h1h,*h1l,*h2h,*h2l,*A2h,*A2l;
    bf16 *Wih,*Wil,*Wr0h,*Wr0l,*Wr1h,*Wr1l,*Woh,*Wol;
    float *U;
    cudaGetSymbolAddress((void**)&xTh, g_xTh); cudaGetSymbolAddress((void**)&xTl, g_xTl);
    cudaGetSymbolAddress((void**)&h0h, g_h0h); cudaGetSymbolAddress((void**)&h0l, g_h0l);
    cudaGetSymbolAddress((void**)&U,   g_U);
    cudaGetSymbolAddress((void**)&h1h, g_h1h); cudaGetSymbolAddress((void**)&h1l, g_h1l);
    cudaGetSymbolAddress((void**)&h2h, g_h2h); cudaGetSymbolAddress((void**)&h2l, g_h2l);
    cudaGetSymbolAddress((void**)&A2h, g_A2h); cudaGetSymbolAddress((void**)&A2l, g_A2l);
    cudaGetSymbolAddress((void**)&Wih, g_Wih); cudaGetSymbolAddress((void**)&Wil, g_Wil);
    cudaGetSymbolAddress((void**)&Wr0h, g_Wr0h); cudaGetSymbolAddress((void**)&Wr0l, g_Wr0l);
    cudaGetSymbolAddress((void**)&Wr1h, g_Wr1h); cudaGetSymbolAddress((void**)&Wr1l, g_Wr1l);
    cudaGetSymbolAddress((void**)&Woh, g_Woh); cudaGetSymbolAddress((void**)&Wol, g_Wol);

    cudaFuncSetAttribute(tc_gemm<0>, cudaFuncAttributeMaxDynamicSharedMemorySize, S_TOT);
    cudaFuncSetAttribute(tc_gemm<1>, cudaFuncAttributeMaxDynamicSharedMemorySize, S_TOT);
    cudaFuncSetAttribute(tc_gemm<2>, cudaFuncAttributeMaxDynamicSharedMemorySize, S_TOT);

    // #1 transpose + split input activations
    transpose_kernel<<<M_, 256>>>(inputs, xTh, xTl);
    // #2 fused weight prep (one launch)
    wprep_all<<<3968, 256>>>(W_in, W_rnn, W_out,
                             Wih, Wil, Wr0h, Wr0l, Wr1h, Wr1l, Woh, Wol);

    // #3 input layer GEMM (tanh, split out)  K=832
    tc_gemm<1><<<dim3(512/NT, M_/MT), 128, S_TOT>>>(
        xTh, xTl, KP1, Wih, Wil, KP1,
        nullptr, h0h, h0l, H_, 512, KP1, b_in, nullptr, nullptr);

    // #4 SRU layer 0 GEMM, #5 scan
    tc_gemm<0><<<dim3(H3/NT, M_/MT), 128, S_TOT>>>(
        h0h, h0l, H_, Wr0h, Wr0l, H_,
        U, nullptr, nullptr, H3, H3, H_, nullptr, nullptr, nullptr);
    scan_kernel<<<(B_*H_)/32, 32>>>(U, h0h, h0l, v_rnn, b_rnn, h1h, h1l);

    // #6 SRU layer 1 GEMM (ncu -s 5 -c 1 captures this launch), #7 scan
    tc_gemm<0><<<dim3(H3/NT, M_/MT), 128, S_TOT>>>(
        h1h, h1l, H_, Wr1h, Wr1l, H_,
        U, nullptr, nullptr, H3, H3, H_, nullptr, nullptr, nullptr);
    scan_kernel<<<(B_*H_)/32, 32>>>(U, h1h, h1l, v_rnn + 2*H_, b_rnn + 2*H_, h2h, h2l);

    // #8 fused conv + pool + tanh -> split A2
    convpool_kernel<<<dim3(H_/32, T_/8, B_), 256>>>(conv_k, conv_b, h2h, h2l, A2h, A2l);

    // #9 output GEMM (257 cols) fused sigmoid*input  K=4608
    tc_gemm<2><<<dim3(3, M_/MT), 128, S_TOT>>>(
        A2h, A2l, A2K, Woh, Wol, A2K,
        nullptr, nullptr, nullptr, 0, INDIM, A2K, b_out + INDIM, inputs, out);
}

// round 16
// speedup vs baseline: 1.5042x; 1.5042x over previous
#include <cuda_runtime.h>
#include <cuda_bf16.h>
#include <math.h>
#include <stdint.h>

#define B_    16
#define T_    1000
#define INDIM 257
#define FEAT  771
#define H_    512
#define KN    9
#define KS    6
#define M_    (B_*T_)        /* 16000 rows, time-major: row = t*B + b */
#define H3    (3*H_)         /* 1536 */
#define A2K   (H_*KN)        /* 4608 */
#define KP1   832            /* padded K for input GEMM (771 -> 832, /64) */
#define PLANE ((size_t)M_*H_)

/* tc_gemm tiling */
#define MT 128
#define NT 128
#define KC 64                /* K chunk: 64 bf16 per 128B smem row */

/* tc_gemm smem layout (single buffer) */
#define S_TM   0
#define S_MB   8
#define S_AH   1024
#define S_AL   (S_AH + 16384)
#define S_BH   (S_AL + 16384)
#define S_BL   (S_BH + 16384)
#define S_TOT  (S_BL + 16384)

#if defined(__CUDA_ARCH_FEAT_SM103_ALL) || defined(__CUDA_ARCH_FEAT_SM100_ALL)
#define HAS_TCGEN05 1
#endif

typedef __nv_bfloat16 bf16;

/* ---------------- scratch (device globals; no allocation allowed) -------- */
__device__ __align__(16) bf16 g_xTh[(size_t)M_*KP1];
__device__ __align__(16) bf16 g_xTl[(size_t)M_*KP1];
__device__ __align__(16) bf16 g_h0h[(size_t)M_*H_];
__device__ __align__(16) bf16 g_h0l[(size_t)M_*H_];
__device__ float g_U  [(size_t)M_*H3];
__device__ __align__(16) bf16 g_h1h[(size_t)M_*H_];
__device__ __align__(16) bf16 g_h1l[(size_t)M_*H_];
__device__ __align__(16) bf16 g_h2h[(size_t)M_*H_];
__device__ __align__(16) bf16 g_h2l[(size_t)M_*H_];
__device__ __align__(16) bf16 g_A2h[(size_t)M_*A2K];
__device__ __align__(16) bf16 g_A2l[(size_t)M_*A2K];
__device__ __align__(16) bf16 g_Wih[(size_t)H_*KP1];     // W_in^T  [512][832]
__device__ __align__(16) bf16 g_Wil[(size_t)H_*KP1];
__device__ __align__(16) bf16 g_Wr0h[(size_t)H3*H_];     // W_rnn0^T [1536][512]
__device__ __align__(16) bf16 g_Wr0l[(size_t)H3*H_];
__device__ __align__(16) bf16 g_Wr1h[(size_t)H3*H_];
__device__ __align__(16) bf16 g_Wr1l[(size_t)H3*H_];
__device__ __align__(16) bf16 g_Woh[(size_t)384*A2K];    // W_out slice^T (rows>=257 zero)
__device__ __align__(16) bf16 g_Wol[(size_t)384*A2K];

/* ---------------- generic helpers (legal on all targets) ----------------- */
__device__ __forceinline__ void bsplit(float x, bf16 &h, bf16 &l) {
    h = __float2bfloat16_rn(x);
    l = __float2bfloat16_rn(x - __bfloat162float(h));
}
__device__ __forceinline__ float brecon(bf16 h, bf16 l) {
    return __bfloat162float(h) + __bfloat162float(l);
}

#ifdef HAS_TCGEN05
__device__ __forceinline__ uint32_t smem_u32(const void* p) {
    uint32_t a;
    asm("{ .reg .u64 t; cvta.to.shared.u64 t, %1; cvt.u32.u64 %0, t; }" : "=r"(a) : "l"(p));
    return a;
}
__device__ __forceinline__ uint32_t elect1() {
    uint32_t p;
    asm volatile("{ .reg .pred p; elect.sync _|p, 0xFFFFFFFF; selp.b32 %0, 1, 0, p; }" : "=r"(p));
    return p;
}
__device__ __forceinline__ void mbar_init(uint32_t a, uint32_t c) {
    asm volatile("mbarrier.init.shared.b64 [%0], %1;" :: "r"(a), "r"(c) : "memory");
}
__device__ __forceinline__ void mbar_inval(uint32_t a) {
    asm volatile("mbarrier.inval.shared.b64 [%0];" :: "r"(a) : "memory");
}
__device__ __forceinline__ void mbar_wait(uint32_t a, uint32_t ph) {
    asm volatile(
        "{\n\t.reg .pred P;\n\t"
        "LW%=:\n\t"
        "mbarrier.try_wait.parity.acquire.cta.shared::cta.b64 P, [%0], %1, 0x989680;\n\t"
        "@P bra LD%=;\n\t"
        "bra LW%=;\n\t"
        "LD%=:\n\t}"
        :: "r"(a), "r"(ph) : "memory");
}
__device__ __forceinline__ void tm_alloc(uint32_t smem_dst, uint32_t ncols) {
    asm volatile("tcgen05.alloc.cta_group::1.sync.aligned.shared::cta.b32 [%0], %1;"
                 :: "r"(smem_dst), "r"(ncols) : "memory");
}
__device__ __forceinline__ void tm_relinq() {
    asm volatile("tcgen05.relinquish_alloc_permit.cta_group::1.sync.aligned;");
}
__device__ __forceinline__ void tm_dealloc(uint32_t tm, uint32_t ncols) {
    asm volatile("tcgen05.dealloc.cta_group::1.sync.aligned.b32 %0, %1;" :: "r"(tm), "r"(ncols));
}
__device__ __forceinline__ void tm_commit(uint32_t mbar) {
    asm volatile("tcgen05.commit.cta_group::1.mbarrier::arrive::one.shared::cluster.b64 [%0];"
                 :: "r"(mbar) : "memory");
}
__device__ __forceinline__ void fence_after() {
    asm volatile("tcgen05.fence::after_thread_sync;" ::: "memory");
}
__device__ __forceinline__ void fence_async_shared() {
    asm volatile("fence.proxy.async.shared::cta;" ::: "memory");
}
__device__ __forceinline__ void mma_bf16_ss(uint32_t d, uint64_t a, uint64_t b,
                                            uint32_t idesc, bool en) {
    uint32_t e = en ? 1u : 0u;
    asm volatile(
        "{\n\t.reg .pred p;\n\t"
        "setp.ne.u32 p, %5, 0;\n\t"
        "tcgen05.mma.cta_group::1.kind::f16 [%0], %1, %2, %3, {%4, %4, %4, %4}, p;\n\t}"
        :: "r"(d), "l"(a), "l"(b), "r"(idesc), "r"(0u), "r"(e) : "memory");
}
#define LDTM_X32(r, addr) \
    asm volatile( \
        "tcgen05.ld.sync.aligned.32x32b.x32.b32 " \
        "{%0,%1,%2,%3,%4,%5,%6,%7,%8,%9,%10,%11,%12,%13,%14,%15," \
        "%16,%17,%18,%19,%20,%21,%22,%23,%24,%25,%26,%27,%28,%29,%30,%31}, [%32];" \
        : "=r"((r)[0]),"=r"((r)[1]),"=r"((r)[2]),"=r"((r)[3]), \
          "=r"((r)[4]),"=r"((r)[5]),"=r"((r)[6]),"=r"((r)[7]), \
          "=r"((r)[8]),"=r"((r)[9]),"=r"((r)[10]),"=r"((r)[11]), \
          "=r"((r)[12]),"=r"((r)[13]),"=r"((r)[14]),"=r"((r)[15]), \
          "=r"((r)[16]),"=r"((r)[17]),"=r"((r)[18]),"=r"((r)[19]), \
          "=r"((r)[20]),"=r"((r)[21]),"=r"((r)[22]),"=r"((r)[23]), \
          "=r"((r)[24]),"=r"((r)[25]),"=r"((r)[26]),"=r"((r)[27]), \
          "=r"((r)[28]),"=r"((r)[29]),"=r"((r)[30]),"=r"((r)[31]) \
        : "r"(addr))
__device__ __forceinline__ void wait_ld() {
    asm volatile("tcgen05.wait::ld.sync.aligned;" ::: "memory");
}
__device__ __forceinline__ uint64_t mk_desc(uint32_t addr) {
    return ((uint64_t)2 << 61) | ((uint64_t)1 << 46) | ((uint64_t)64 << 32)
         | ((uint64_t)1 << 16) | (((uint64_t)addr >> 4) & 0x3FFF);
}
#endif /* HAS_TCGEN05 */

/* ---------------- transpose (b,t,f)->(t,b,f), bf16 split, K-pad ---------- */
__global__ void transpose_kernel(const float* __restrict__ in,
                                 bf16* __restrict__ xh, bf16* __restrict__ xl) {
    int row = blockIdx.x;                  // t*B + b
    int t = row >> 4, b = row & 15;
    const float* src = in + ((size_t)b*T_ + t)*FEAT;
    bf16* dh = xh + (size_t)row*KP1;
    bf16* dl = xl + (size_t)row*KP1;
    for (int f = threadIdx.x; f < KP1; f += blockDim.x) {
        float v = (f < FEAT) ? src[f] : 0.f;
        bf16 h, l; bsplit(v, h, l);
        dh[f] = h; dl[f] = l;
    }
}

/* ---------------- fused weight prep (ONE launch): transpose+split+pad ---- */
__global__ void wprep_all(const float* __restrict__ Wi, const float* __restrict__ Wr,
                          const float* __restrict__ Wo,
                          bf16* __restrict__ Wih, bf16* __restrict__ Wil,
                          bf16* __restrict__ Wr0h, bf16* __restrict__ Wr0l,
                          bf16* __restrict__ Wr1h, bf16* __restrict__ Wr1l,
                          bf16* __restrict__ Woh, bf16* __restrict__ Wol)
{
    int bid = blockIdx.x;
    const float* W; int srcld, n0, ncols, K, Kpad; bf16 *dh, *dl; int n;
    if (bid < 512) {
        n = bid; W = Wi; srcld = H_; n0 = 0; ncols = H_; K = FEAT; Kpad = KP1;
        dh = Wih + (size_t)n*Kpad; dl = Wil + (size_t)n*Kpad;
    } else if (bid < 2048) {
        n = bid - 512; W = Wr; srcld = H3; n0 = 0; ncols = H3; K = H_; Kpad = H_;
        dh = Wr0h + (size_t)n*Kpad; dl = Wr0l + (size_t)n*Kpad;
    } else if (bid < 3584) {
        n = bid - 2048; W = Wr + (size_t)H_*H3; srcld = H3; n0 = 0; ncols = H3; K = H_; Kpad = H_;
        dh = Wr1h + (size_t)n*Kpad; dl = Wr1l + (size_t)n*Kpad;
    } else {
        n = bid - 3584; W = Wo; srcld = FEAT; n0 = INDIM; ncols = INDIM; K = A2K; Kpad = A2K;
        dh = Woh + (size_t)n*Kpad; dl = Wol + (size_t)n*Kpad;
    }
    bool nv = (n < ncols);
    for (int k = threadIdx.x; k < Kpad; k += blockDim.x) {
        float v = (nv && k < K) ? W[(size_t)k*srcld + n0 + n] : 0.f;
        bf16 h, l; bsplit(v, h, l);
        dh[k] = h; dl[k] = l;
    }
}

/* ---------------- GEMM 128x128 tile, bf16 2-split, register prefetch ------
 * C[M,N] = (Ah+Al)[M,K] @ (Bh+Bl)^T  with Bt stored [N][K] (bf16 planes).
 * Products kept: AhBh + AlBh + AhBl (err ~2^-18 rel).
 * Single smem buffer; next chunk's LDGs issued right after the current
 * chunk's MMA dispatch so load latency hides under the MMA chain.
 * Epilogue stages 32x32 tiles via padded smem so stores are coalesced rows.
 * EPI 0: C = acc (ldc)
 * EPI 1: t = tanh(acc + bias[n]); Chi/Clo = bsplit(t)   (ldc)
 * EPI 2: out[row,n] = sigmoid(acc+bias[n]) * inp[row, 257+n], n < N(=257)
 */
template<int EPI>
__global__ __launch_bounds__(128)
void tc_gemm(const bf16* __restrict__ Ahi, const bf16* __restrict__ Alo, int lda,
             const bf16* __restrict__ Bhi, const bf16* __restrict__ Blo, int ldb,
             float* __restrict__ C, bf16* __restrict__ Chi, bf16* __restrict__ Clo,
             int ldc, int N, int K,
             const float* __restrict__ bias,
             const float* __restrict__ inp, float* __restrict__ outp)
{
    extern __shared__ char smem[];
    int tid = threadIdx.x;
    int mBase = blockIdx.y * MT, nBase = blockIdx.x * NT;

#ifdef HAS_TCGEN05
    uint32_t sb = smem_u32(smem);
    int wid = tid >> 5, lane = tid & 31;

    if (wid == 0) { tm_alloc(sb + S_TM, 128); tm_relinq(); }
    if (tid == 0) mbar_init(sb + S_MB, 1);
    __syncthreads();
    uint32_t tmem;
    asm volatile("ld.shared.b32 %0, [%1];" : "=r"(tmem) : "r"(sb + S_TM));

    /* kind::f16 bf16 idesc: dtype=F32(1<<4), atype=BF16(1<<7), btype=BF16(1<<10) */
    const uint32_t idesc = (1u << 4) | (1u << 7) | (1u << 10)
                         | ((NT / 8) << 17) | ((MT / 16) << 24);
    uint64_t adh = mk_desc(sb + S_AH), adl = mk_desc(sb + S_AL);
    uint64_t bdh = mk_desc(sb + S_BH), bdl = mk_desc(sb + S_BL);

    /* per-thread row/col mapping: idx=j*128+tid; 8 lanes cover one 128B row */
    int swoj[8]; size_t oAj[8], oBj[8];
    #pragma unroll
    for (int j = 0; j < 8; j++) {
        int idx = j*128 + tid;
        int r = idx >> 3, c = idx & 7;
        oAj[j] = (size_t)(mBase + r)*lda + c*8;
        oBj[j] = (size_t)(nBase + r)*ldb + c*8;
        swoj[j] = (int)(((uint32_t)(r*128 + c*16)) ^ (((uint32_t)(r & 7)) << 4));
    }

    float4 rA0[8], rA1[8], rB0[8], rB1[8];
    /* prologue: prefetch chunk 0 */
    #pragma unroll
    for (int j = 0; j < 8; j++) {
        rA0[j] = *reinterpret_cast<const float4*>(Ahi + oAj[j]);
        rA1[j] = *reinterpret_cast<const float4*>(Alo + oAj[j]);
        rB0[j] = *reinterpret_cast<const float4*>(Bhi + oBj[j]);
        rB1[j] = *reinterpret_cast<const float4*>(Blo + oBj[j]);
    }

    int nch = K / KC;
    uint32_t ph = 0;
    for (int ch = 0; ch < nch; ch++) {
        if (ch > 0) { mbar_wait(sb + S_MB, ph); ph ^= 1; }
        #pragma unroll
        for (int j = 0; j < 8; j++) {
            *reinterpret_cast<float4*>(smem + S_AH + swoj[j]) = rA0[j];
            *reinterpret_cast<float4*>(smem + S_AL + swoj[j]) = rA1[j];
            *reinterpret_cast<float4*>(smem + S_BH + swoj[j]) = rB0[j];
            *reinterpret_cast<float4*>(smem + S_BL + swoj[j]) = rB1[j];
        }
        fence_async_shared();
        __syncthreads();
        if (wid == 0 && elect1()) {
            #pragma unroll
            for (int ks = 0; ks < 4; ks++) {          // k-step = 16 bf16 = 32B = +2 units
                uint64_t off = (uint64_t)(ks * 2);
                mma_bf16_ss(tmem, adh + off, bdh + off, idesc, !(ch == 0 && ks == 0));
                mma_bf16_ss(tmem, adl + off, bdh + off, idesc, true);
                mma_bf16_ss(tmem, adh + off, bdl + off, idesc, true);
            }
            tm_commit(sb + S_MB);
        }
        /* prefetch next chunk while MMAs run; next wait hides the latency */
        if (ch + 1 < nch) {
            int k1 = (ch + 1) * KC;
            #pragma unroll
            for (int j = 0; j < 8; j++) {
                rA0[j] = *reinterpret_cast<const float4*>(Ahi + oAj[j] + k1);
                rA1[j] = *reinterpret_cast<const float4*>(Alo + oAj[j] + k1);
                rB0[j] = *reinterpret_cast<const float4*>(Bhi + oBj[j] + k1);
                rB1[j] = *reinterpret_cast<const float4*>(Blo + oBj[j] + k1);
            }
        }
    }
    mbar_wait(sb + S_MB, (uint32_t)((nch - 1) & 1));
    fence_after();

    /* epilogue: warp w owns rows m0..m0+31; columns in 4 groups of 32.
       EPI0/1: stage 32x32 via padded smem (mainloop tiles now free) so
       global stores are coalesced full rows. */
    int m0 = mBase + wid*32;
    int m = m0 + lane;
    float* stg = reinterpret_cast<float*>(smem + S_AH) + wid*(32*33);
    #pragma unroll
    for (int cb = 0; cb < 4; cb++) {
        uint32_t d[32];
        LDTM_X32(d, tmem + cb*32);
        wait_ld();
        int nb = nBase + cb*32;
        if (EPI == 2) {
            int b = m & 15, t = m >> 4;
            size_t row = (size_t)b*T_ + t;
            #pragma unroll
            for (int c = 0; c < 32; c++) {
                int n = nb + c;
                if (n < N) {
                    float v = __uint_as_float(d[c]) + bias[n];
                    float s = 1.f / (1.f + __expf(-v));
                    outp[row*INDIM + n] = s * inp[row*FEAT + INDIM + n];
                }
            }
        } else {
            #pragma unroll
            for (int c = 0; c < 32; c++) stg[c*33 + lane] = __uint_as_float(d[c]);
            __syncwarp();
            if (EPI == 0) {
                int n = nb + lane;
                #pragma unroll 8
                for (int rr = 0; rr < 32; rr++)
                    C[(size_t)(m0+rr)*ldc + n] = stg[lane*33 + rr];
            } else {
                int n = nb + lane;
                float bn = bias[n];
                #pragma unroll 8
                for (int rr = 0; rr < 32; rr++) {
                    float t = tanhf(stg[lane*33 + rr] + bn);
                    bf16 h, l; bsplit(t, h, l);
                    Chi[(size_t)(m0+rr)*ldc + n] = h;
                    Clo[(size_t)(m0+rr)*ldc + n] = l;
                }
            }
            __syncwarp();
        }
    }

    __syncthreads();
    if (tid == 0) mbar_inval(sb + S_MB);
    __syncthreads();
    if (wid == 0) tm_dealloc(tmem, 128);

#else  /* ---------- SIMT FFMA fallback (non sm_103a targets) ------------- */
    float* As = reinterpret_cast<float*>(smem);            // [128][33]
    float* Bs = reinterpret_cast<float*>(smem + 17408);    // [128][33]
    const bf16* arh = Ahi + (size_t)(mBase + tid)*lda;
    const bf16* arl = Alo + (size_t)(mBase + tid)*lda;
    const bf16* brh = Bhi + (size_t)(nBase + tid)*ldb;
    const bf16* brl = Blo + (size_t)(nBase + tid)*ldb;

    for (int half = 0; half < 2; half++) {
        float acc[64];
        #pragma unroll
        for (int j = 0; j < 64; j++) acc[j] = 0.f;
        for (int k0 = 0; k0 < K; k0 += 32) {
            for (int q = 0; q < 32; q++) {
                As[tid*33 + q] = brecon(arh[k0+q], arl[k0+q]);
                Bs[tid*33 + q] = brecon(brh[k0+q], brl[k0+q]);
            }
            __syncthreads();
            for (int kk = 0; kk < 32; kk++) {
                float a = As[tid*33 + kk];
                #pragma unroll
                for (int j = 0; j < 64; j++)
                    acc[j] = fmaf(a, Bs[(half*64 + j)*33 + kk], acc[j]);
            }
            __syncthreads();
        }
        int m = mBase + tid;
        int nb = nBase + half*64;
        if (EPI == 0) {
            float* dst = C + (size_t)m*ldc + nb;
            for (int j = 0; j < 64; j++) dst[j] = acc[j];
        } else if (EPI == 1) {
            for (int j = 0; j < 64; j++) {
                int n = nb + j;
                float t = tanhf(acc[j] + bias[n]);
                bf16 h, l; bsplit(t, h, l);
                Chi[(size_t)m*ldc + n] = h;
                Clo[(size_t)m*ldc + n] = l;
            }
        } else {
            int b = m & 15, t = m >> 4;
            size_t row = (size_t)b*T_ + t;
            for (int j = 0; j < 64; j++) {
                int n = nb + j;
                if (n < N) {
                    float v = acc[j] + bias[n];
                    float s = 1.f / (1.f + __expf(-v));
                    outp[row*INDIM + n] = s * inp[row*FEAT + INDIM + n];
                }
            }
        }
    }
#endif
}

/* ---------------- SRU scan: bf16 X in, bf16 H out, pipelined ------------- */
#define SUN 8
__global__ void scan_kernel(const float* __restrict__ U,
                            const bf16* __restrict__ Xh, const bf16* __restrict__ Xl,
                            const float* __restrict__ v, const float* __restrict__ bb,
                            bf16* __restrict__ Hh, bf16* __restrict__ Hl)
{
    int idx = blockIdx.x * blockDim.x + threadIdx.x;   // 0..B*H-1
    int b = idx >> 9, h = idx & (H_-1);
    float vf = v[h], vr = v[H_ + h];
    float bf = bb[h], br = bb[H_ + h];
    const float* Ub  = U  + (size_t)b*H3 + h;
    const bf16* Xhb = Xh + (size_t)b*H_ + h;
    const bf16* Xlb = Xl + (size_t)b*H_ + h;
    bf16* Hhb = Hh + (size_t)b*H_ + h;
    bf16* Hlb = Hl + (size_t)b*H_ + h;

    float cxt[SUN], cfp[SUN], crp[SUN], cxn[SUN];
    #pragma unroll
    for (int u = 0; u < SUN; u++) {
        size_t o3 = (size_t)u * (B_*H3);
        size_t o1 = (size_t)u * (B_*H_);
        cxt[u] = Ub[o3]; cfp[u] = Ub[o3 + H_]; crp[u] = Ub[o3 + 2*H_];
        cxn[u] = brecon(Xhb[o1], Xlb[o1]);
    }
    float c = 0.f;
    for (int t0 = 0; t0 < T_; t0 += SUN) {
        float nxt[SUN], nfp[SUN], nrp[SUN], nxn[SUN];
        bool more = (t0 + SUN < T_);
        #pragma unroll
        for (int u = 0; u < SUN; u++) {
            int t = t0 + SUN + u;
            size_t o3 = (size_t)t * (B_*H3);
            size_t o1 = (size_t)t * (B_*H_);
            if (more) {
                nxt[u] = Ub[o3]; nfp[u] = Ub[o3 + H_]; nrp[u] = Ub[o3 + 2*H_];
                nxn[u] = brecon(Xhb[o1], Xlb[o1]);
            } else { nxt[u] = nfp[u] = nrp[u] = nxn[u] = 0.f; }
        }
        #pragma unroll
        for (int u = 0; u < SUN; u++) {
            float f = 1.f / (1.f + __expf(-(fmaf(vf, c, cfp[u]) + bf)));
            float cn = fmaf(f, c - cxt[u], cxt[u]);
            float r = 1.f / (1.f + __expf(-(fmaf(vr, c, crp[u]) + br)));
            float hv = fmaf(r, cn - cxn[u], cxn[u]);
            bf16 hh, hl; bsplit(hv, hh, hl);
            size_t o1 = (size_t)(t0+u) * (B_*H_);
            Hhb[o1] = hh; Hlb[o1] = hl;
            c = cn;
        }
        #pragma unroll
        for (int u = 0; u < SUN; u++) {
            cxt[u] = nxt[u]; cfp[u] = nfp[u]; crp[u] = nrp[u]; cxn[u] = nxn[u];
        }
    }
}

/* ---------------- fused conv6x6 + maxpool3x3 + tanh, bf16 split output --- */
__global__ __launch_bounds__(256)
void convpool_kernel(const float* __restrict__ w, const float* __restrict__ cb,
                     const bf16* __restrict__ inh, const bf16* __restrict__ inl,
                     bf16* __restrict__ A2h, bf16* __restrict__ A2l)
{
    __shared__ float ws[KN][KS][KS];
    __shared__ float bs[KN];
    __shared__ float xin[15][40];
    __shared__ float cv[KN][10][36];
    __shared__ float po[8][32*KN];

    int b  = blockIdx.z;
    int t0 = blockIdx.y * 8;
    int h0 = blockIdx.x * 32;
    int tid = threadIdx.x;

    for (int i = tid; i < KN*KS*KS; i += 256) (&ws[0][0][0])[i] = w[i];
    if (tid < KN) bs[tid] = cb[tid];
    for (int i = tid; i < 15*39; i += 256) {
        int r = i / 39, cc = i % 39;
        int t = t0 - 4 + r, h = h0 - 4 + cc;
        float val = 0.f;
        if (t >= 0 && t < T_ && h >= 0 && h < H_) {
            size_t o = ((size_t)t*B_ + b)*H_ + h;
            val = brecon(inh[o], inl[o]);
        }
        xin[r][cc] = val;
    }
    __syncthreads();

    for (int p = tid; p < 10*34; p += 256) {
        int r = p / 34, cc = p % 34;
        int tt = t0 - 1 + r, hh = h0 - 1 + cc;
        float acc[KN];
        #pragma unroll
        for (int kn = 0; kn < KN; kn++) acc[kn] = 0.f;
        #pragma unroll
        for (int i = 0; i < KS; i++)
            #pragma unroll
            for (int j = 0; j < KS; j++) {
                float x = xin[r + i][cc + j];
                #pragma unroll
                for (int kn = 0; kn < KN; kn++)
                    acc[kn] = fmaf(ws[kn][i][j], x, acc[kn]);
            }
        bool valid = (tt >= 0 && tt < T_ && hh >= 0 && hh < H_);
        #pragma unroll
        for (int kn = 0; kn < KN; kn++)
            cv[kn][r][cc] = valid ? acc[kn] : -3.0e38f;
    }
    __syncthreads();

    {
        int ht = tid & 31, tt = tid >> 5;
        #pragma unroll
        for (int kn = 0; kn < KN; kn++) {
            float m = -3.0e38f;
            #pragma unroll
            for (int dt = 0; dt < 3; dt++)
                #pragma unroll
                for (int dh = 0; dh < 3; dh++)
                    m = fmaxf(m, cv[kn][tt + dt][ht + dh]);
            po[tt][ht*KN + kn] = tanhf(m + bs[kn]);
        }
    }
    __syncthreads();

    for (int i = tid; i < 8*32*KN; i += 256) {
        int row = i / (32*KN), f = i % (32*KN);
        size_t o = ((size_t)(t0 + row)*B_ + b)*A2K + (size_t)h0*KN + f;
        bf16 h, l; bsplit(po[row][f], h, l);
        A2h[o] = h; A2l[o] = l;
    }
}

/* ---------------- driver -------------------------------------------------- */
extern "C" void kernel_launch(void* const* d_in, const int* in_sizes, int n_in,
                              void* d_out, int out_size)
{
    const float* inputs = (const float*)d_in[0];
    const float* W_in   = (const float*)d_in[1];
    const float* b_in   = (const float*)d_in[2];
    const float* W_rnn  = (const float*)d_in[3];
    const float* v_rnn  = (const float*)d_in[4];
    const float* b_rnn  = (const float*)d_in[5];
    const float* conv_k = (const float*)d_in[6];
    const float* conv_b = (const float*)d_in[7];
    const float* W_out  = (const float*)d_in[8];
    const float* b_out  = (const float*)d_in[9];
    float* out = (float*)d_out;

    bf16 *xTh,*xTl,*h0h,*h0l,*h1h,*h1l,*h2h,*h2l,*A2h,*A2l;
    bf16 *Wih,*Wil,*Wr0h,*Wr0l,*Wr1h,*Wr1l,*Woh,*Wol;
    float *U;
    cudaGetSymbolAddress((void**)&xTh, g_xTh); cudaGetSymbolAddress((void**)&xTl, g_xTl);
    cudaGetSymbolAddress((void**)&h0h, g_h0h); cudaGetSymbolAddress((void**)&h0l, g_h0l);
    cudaGetSymbolAddress((void**)&U,   g_U);
    cudaGetSymbolAddress((void**)&h1h, g_h1h); cudaGetSymbolAddress((void**)&h1l, g_h1l);
    cudaGetSymbolAddress((void**)&h2h, g_h2h); cudaGetSymbolAddress((void**)&h2l, g_h2l);
    cudaGetSymbolAddress((void**)&A2h, g_A2h); cudaGetSymbolAddress((void**)&A2l, g_A2l);
    cudaGetSymbolAddress((void**)&Wih, g_Wih); cudaGetSymbolAddress((void**)&Wil, g_Wil);
    cudaGetSymbolAddress((void**)&Wr0h, g_Wr0h); cudaGetSymbolAddress((void**)&Wr0l, g_Wr0l);
    cudaGetSymbolAddress((void**)&Wr1h, g_Wr1h); cudaGetSymbolAddress((void**)&Wr1l, g_Wr1l);
    cudaGetSymbolAddress((void**)&Woh, g_Woh); cudaGetSymbolAddress((void**)&Wol, g_Wol);

    cudaFuncSetAttribute(tc_gemm<0>, cudaFuncAttributeMaxDynamicSharedMemorySize, S_TOT);
    cudaFuncSetAttribute(tc_gemm<1>, cudaFuncAttributeMaxDynamicSharedMemorySize, S_TOT);
    cudaFuncSetAttribute(tc_gemm<2>, cudaFuncAttributeMaxDynamicSharedMemorySize, S_TOT);

    // #1 transpose + split input activations
    transpose_kernel<<<M_, 256>>>(inputs, xTh, xTl);
    // #2 fused weight prep (one launch)
    wprep_all<<<3968, 256>>>(W_in, W_rnn, W_out,
                             Wih, Wil, Wr0h, Wr0l, Wr1h, Wr1l, Woh, Wol);

    // #3 input layer GEMM (tanh, split out)  K=832
    tc_gemm<1><<<dim3(512/NT, M_/MT), 128, S_TOT>>>(
        xTh, xTl, KP1, Wih, Wil, KP1,
        nullptr, h0h, h0l, H_, 512, KP1, b_in, nullptr, nullptr);

    // #4 SRU layer 0 GEMM, #5 scan
    tc_gemm<0><<<dim3(H3/NT, M_/MT), 128, S_TOT>>>(
        h0h, h0l, H_, Wr0h, Wr0l, H_,
        U, nullptr, nullptr, H3, H3, H_, nullptr, nullptr, nullptr);
    scan_kernel<<<(B_*H_)/128, 128>>>(U, h0h, h0l, v_rnn, b_rnn, h1h, h1l);

    // #6 SRU layer 1 GEMM (ncu -s 5 -c 1 captures this launch), #7 scan
    tc_gemm<0><<<dim3(H3/NT, M_/MT), 128, S_TOT>>>(
        h1h, h1l, H_, Wr1h, Wr1l, H_,
        U, nullptr, nullptr, H3, H3, H_, nullptr, nullptr, nullptr);
    scan_kernel<<<(B_*H_)/128, 128>>>(U, h1h, h1l, v_rnn + 2*H_, b_rnn + 2*H_, h2h, h2l);

    // #8 fused conv + pool + tanh -> split A2
    convpool_kernel<<<dim3(H_/32, T_/8, B_), 256>>>(conv_k, conv_b, h2h, h2l, A2h, A2l);

    // #9 output GEMM (257 cols) fused sigmoid*input  K=4608
    tc_gemm<2><<<dim3(3, M_/MT), 128, S_TOT>>>(
        A2h, A2l, A2K, Woh, Wol, A2K,
        nullptr, nullptr, nullptr, 0, INDIM, A2K, b_out + INDIM, inputs, out);
}

// round 17
// speedup vs baseline: 1.5387x; 1.0230x over previous
#include <cuda_runtime.h>
#include <cuda_bf16.h>
#include <math.h>
#include <stdint.h>

#define B_    16
#define T_    1000
#define INDIM 257
#define FEAT  771
#define H_    512
#define KN    9
#define KS    6
#define M_    (B_*T_)        /* 16000 rows, time-major: row = t*B + b */
#define H3    (3*H_)         /* 1536 */
#define A2K   (H_*KN)        /* 4608 */
#define KP1   832            /* padded K for input GEMM (771 -> 832, /64) */
#define PLANE ((size_t)M_*H_)

/* tc_gemm tiling */
#define MT 128
#define NT 128
#define KC 64                /* K chunk: 64 bf16 per 128B smem row */

/* tc_gemm smem layout (single buffer) */
#define S_TM   0
#define S_MB   8
#define S_AH   1024
#define S_AL   (S_AH + 16384)
#define S_BH   (S_AL + 16384)
#define S_BL   (S_BH + 16384)
#define S_TOT  (S_BL + 16384)

/* tc_out smem: header + 8 planes (AH,AL,B0H,B0L,B1H,B1L,B2H,B2L) */
#define SO_TILE 1024
#define SO_TOT  (SO_TILE + 8*16384)

#if defined(__CUDA_ARCH_FEAT_SM103_ALL) || defined(__CUDA_ARCH_FEAT_SM100_ALL)
#define HAS_TCGEN05 1
#endif

typedef __nv_bfloat16 bf16;

/* ---------------- scratch (device globals; no allocation allowed) -------- */
__device__ __align__(16) bf16 g_xTh[(size_t)M_*KP1];
__device__ __align__(16) bf16 g_xTl[(size_t)M_*KP1];
__device__ __align__(16) bf16 g_h0h[(size_t)M_*H_];
__device__ __align__(16) bf16 g_h0l[(size_t)M_*H_];
__device__ float g_U  [(size_t)M_*H3];
__device__ __align__(16) bf16 g_h1h[(size_t)M_*H_];
__device__ __align__(16) bf16 g_h1l[(size_t)M_*H_];
__device__ __align__(16) bf16 g_h2h[(size_t)M_*H_];
__device__ __align__(16) bf16 g_h2l[(size_t)M_*H_];
__device__ __align__(16) bf16 g_A2h[(size_t)M_*A2K];
__device__ __align__(16) bf16 g_A2l[(size_t)M_*A2K];
__device__ __align__(16) bf16 g_Wih[(size_t)H_*KP1];     // W_in^T  [512][832]
__device__ __align__(16) bf16 g_Wil[(size_t)H_*KP1];
__device__ __align__(16) bf16 g_Wr0h[(size_t)H3*H_];     // W_rnn0^T [1536][512]
__device__ __align__(16) bf16 g_Wr0l[(size_t)H3*H_];
__device__ __align__(16) bf16 g_Wr1h[(size_t)H3*H_];
__device__ __align__(16) bf16 g_Wr1l[(size_t)H3*H_];
__device__ __align__(16) bf16 g_Woh[(size_t)384*A2K];    // W_out slice^T (rows>=257 zero)
__device__ __align__(16) bf16 g_Wol[(size_t)384*A2K];

/* ---------------- generic helpers (legal on all targets) ----------------- */
__device__ __forceinline__ void bsplit(float x, bf16 &h, bf16 &l) {
    h = __float2bfloat16_rn(x);
    l = __float2bfloat16_rn(x - __bfloat162float(h));
}
__device__ __forceinline__ float brecon(bf16 h, bf16 l) {
    return __bfloat162float(h) + __bfloat162float(l);
}

#ifdef HAS_TCGEN05
__device__ __forceinline__ uint32_t smem_u32(const void* p) {
    uint32_t a;
    asm("{ .reg .u64 t; cvta.to.shared.u64 t, %1; cvt.u32.u64 %0, t; }" : "=r"(a) : "l"(p));
    return a;
}
__device__ __forceinline__ uint32_t elect1() {
    uint32_t p;
    asm volatile("{ .reg .pred p; elect.sync _|p, 0xFFFFFFFF; selp.b32 %0, 1, 0, p; }" : "=r"(p));
    return p;
}
__device__ __forceinline__ void mbar_init(uint32_t a, uint32_t c) {
    asm volatile("mbarrier.init.shared.b64 [%0], %1;" :: "r"(a), "r"(c) : "memory");
}
__device__ __forceinline__ void mbar_inval(uint32_t a) {
    asm volatile("mbarrier.inval.shared.b64 [%0];" :: "r"(a) : "memory");
}
__device__ __forceinline__ void mbar_wait(uint32_t a, uint32_t ph) {
    asm volatile(
        "{\n\t.reg .pred P;\n\t"
        "LW%=:\n\t"
        "mbarrier.try_wait.parity.acquire.cta.shared::cta.b64 P, [%0], %1, 0x989680;\n\t"
        "@P bra LD%=;\n\t"
        "bra LW%=;\n\t"
        "LD%=:\n\t}"
        :: "r"(a), "r"(ph) : "memory");
}
__device__ __forceinline__ void tm_alloc(uint32_t smem_dst, uint32_t ncols) {
    asm volatile("tcgen05.alloc.cta_group::1.sync.aligned.shared::cta.b32 [%0], %1;"
                 :: "r"(smem_dst), "r"(ncols) : "memory");
}
__device__ __forceinline__ void tm_relinq() {
    asm volatile("tcgen05.relinquish_alloc_permit.cta_group::1.sync.aligned;");
}
__device__ __forceinline__ void tm_dealloc(uint32_t tm, uint32_t ncols) {
    asm volatile("tcgen05.dealloc.cta_group::1.sync.aligned.b32 %0, %1;" :: "r"(tm), "r"(ncols));
}
__device__ __forceinline__ void tm_commit(uint32_t mbar) {
    asm volatile("tcgen05.commit.cta_group::1.mbarrier::arrive::one.shared::cluster.b64 [%0];"
                 :: "r"(mbar) : "memory");
}
__device__ __forceinline__ void fence_after() {
    asm volatile("tcgen05.fence::after_thread_sync;" ::: "memory");
}
__device__ __forceinline__ void fence_async_shared() {
    asm volatile("fence.proxy.async.shared::cta;" ::: "memory");
}
__device__ __forceinline__ void mma_bf16_ss(uint32_t d, uint64_t a, uint64_t b,
                                            uint32_t idesc, bool en) {
    uint32_t e = en ? 1u : 0u;
    asm volatile(
        "{\n\t.reg .pred p;\n\t"
        "setp.ne.u32 p, %5, 0;\n\t"
        "tcgen05.mma.cta_group::1.kind::f16 [%0], %1, %2, %3, {%4, %4, %4, %4}, p;\n\t}"
        :: "r"(d), "l"(a), "l"(b), "r"(idesc), "r"(0u), "r"(e) : "memory");
}
#define LDTM_X32(r, addr) \
    asm volatile( \
        "tcgen05.ld.sync.aligned.32x32b.x32.b32 " \
        "{%0,%1,%2,%3,%4,%5,%6,%7,%8,%9,%10,%11,%12,%13,%14,%15," \
        "%16,%17,%18,%19,%20,%21,%22,%23,%24,%25,%26,%27,%28,%29,%30,%31}, [%32];" \
        : "=r"((r)[0]),"=r"((r)[1]),"=r"((r)[2]),"=r"((r)[3]), \
          "=r"((r)[4]),"=r"((r)[5]),"=r"((r)[6]),"=r"((r)[7]), \
          "=r"((r)[8]),"=r"((r)[9]),"=r"((r)[10]),"=r"((r)[11]), \
          "=r"((r)[12]),"=r"((r)[13]),"=r"((r)[14]),"=r"((r)[15]), \
          "=r"((r)[16]),"=r"((r)[17]),"=r"((r)[18]),"=r"((r)[19]), \
          "=r"((r)[20]),"=r"((r)[21]),"=r"((r)[22]),"=r"((r)[23]), \
          "=r"((r)[24]),"=r"((r)[25]),"=r"((r)[26]),"=r"((r)[27]), \
          "=r"((r)[28]),"=r"((r)[29]),"=r"((r)[30]),"=r"((r)[31]) \
        : "r"(addr))
__device__ __forceinline__ void wait_ld() {
    asm volatile("tcgen05.wait::ld.sync.aligned;" ::: "memory");
}
__device__ __forceinline__ uint64_t mk_desc(uint32_t addr) {
    return ((uint64_t)2 << 61) | ((uint64_t)1 << 46) | ((uint64_t)64 << 32)
         | ((uint64_t)1 << 16) | (((uint64_t)addr >> 4) & 0x3FFF);
}
#endif /* HAS_TCGEN05 */

/* ---------------- transpose (b,t,f)->(t,b,f), bf16 split, K-pad ---------- */
__global__ void transpose_kernel(const float* __restrict__ in,
                                 bf16* __restrict__ xh, bf16* __restrict__ xl) {
    int row = blockIdx.x;                  // t*B + b
    int t = row >> 4, b = row & 15;
    const float* src = in + ((size_t)b*T_ + t)*FEAT;
    bf16* dh = xh + (size_t)row*KP1;
    bf16* dl = xl + (size_t)row*KP1;
    for (int f = threadIdx.x; f < KP1; f += blockDim.x) {
        float v = (f < FEAT) ? src[f] : 0.f;
        bf16 h, l; bsplit(v, h, l);
        dh[f] = h; dl[f] = l;
    }
}

/* ---------------- fused weight prep (ONE launch): transpose+split+pad ---- */
__global__ void wprep_all(const float* __restrict__ Wi, const float* __restrict__ Wr,
                          const float* __restrict__ Wo,
                          bf16* __restrict__ Wih, bf16* __restrict__ Wil,
                          bf16* __restrict__ Wr0h, bf16* __restrict__ Wr0l,
                          bf16* __restrict__ Wr1h, bf16* __restrict__ Wr1l,
                          bf16* __restrict__ Woh, bf16* __restrict__ Wol)
{
    int bid = blockIdx.x;
    const float* W; int srcld, n0, ncols, K, Kpad; bf16 *dh, *dl; int n;
    if (bid < 512) {
        n = bid; W = Wi; srcld = H_; n0 = 0; ncols = H_; K = FEAT; Kpad = KP1;
        dh = Wih + (size_t)n*Kpad; dl = Wil + (size_t)n*Kpad;
    } else if (bid < 2048) {
        n = bid - 512; W = Wr; srcld = H3; n0 = 0; ncols = H3; K = H_; Kpad = H_;
        dh = Wr0h + (size_t)n*Kpad; dl = Wr0l + (size_t)n*Kpad;
    } else if (bid < 3584) {
        n = bid - 2048; W = Wr + (size_t)H_*H3; srcld = H3; n0 = 0; ncols = H3; K = H_; Kpad = H_;
        dh = Wr1h + (size_t)n*Kpad; dl = Wr1l + (size_t)n*Kpad;
    } else {
        n = bid - 3584; W = Wo; srcld = FEAT; n0 = INDIM; ncols = INDIM; K = A2K; Kpad = A2K;
        dh = Woh + (size_t)n*Kpad; dl = Wol + (size_t)n*Kpad;
    }
    bool nv = (n < ncols);
    for (int k = threadIdx.x; k < Kpad; k += blockDim.x) {
        float v = (nv && k < K) ? W[(size_t)k*srcld + n0 + n] : 0.f;
        bf16 h, l; bsplit(v, h, l);
        dh[k] = h; dl[k] = l;
    }
}

/* ---------------- GEMM 128x128 tile, bf16 2-split, register prefetch ------
 * EPI 0: C = acc (ldc)
 * EPI 1: t = tanh(acc + bias[n]); Chi/Clo = bsplit(t)   (ldc)
 */
template<int EPI>
__global__ __launch_bounds__(128)
void tc_gemm(const bf16* __restrict__ Ahi, const bf16* __restrict__ Alo, int lda,
             const bf16* __restrict__ Bhi, const bf16* __restrict__ Blo, int ldb,
             float* __restrict__ C, bf16* __restrict__ Chi, bf16* __restrict__ Clo,
             int ldc, int N, int K,
             const float* __restrict__ bias)
{
    extern __shared__ char smem[];
    int tid = threadIdx.x;
    int mBase = blockIdx.y * MT, nBase = blockIdx.x * NT;

#ifdef HAS_TCGEN05
    uint32_t sb = smem_u32(smem);
    int wid = tid >> 5, lane = tid & 31;

    if (wid == 0) { tm_alloc(sb + S_TM, 128); tm_relinq(); }
    if (tid == 0) mbar_init(sb + S_MB, 1);
    __syncthreads();
    uint32_t tmem;
    asm volatile("ld.shared.b32 %0, [%1];" : "=r"(tmem) : "r"(sb + S_TM));

    const uint32_t idesc = (1u << 4) | (1u << 7) | (1u << 10)
                         | ((NT / 8) << 17) | ((MT / 16) << 24);
    uint64_t adh = mk_desc(sb + S_AH), adl = mk_desc(sb + S_AL);
    uint64_t bdh = mk_desc(sb + S_BH), bdl = mk_desc(sb + S_BL);

    int swoj[8]; size_t oAj[8], oBj[8];
    #pragma unroll
    for (int j = 0; j < 8; j++) {
        int idx = j*128 + tid;
        int r = idx >> 3, c = idx & 7;
        oAj[j] = (size_t)(mBase + r)*lda + c*8;
        oBj[j] = (size_t)(nBase + r)*ldb + c*8;
        swoj[j] = (int)(((uint32_t)(r*128 + c*16)) ^ (((uint32_t)(r & 7)) << 4));
    }

    float4 rA0[8], rA1[8], rB0[8], rB1[8];
    #pragma unroll
    for (int j = 0; j < 8; j++) {
        rA0[j] = *reinterpret_cast<const float4*>(Ahi + oAj[j]);
        rA1[j] = *reinterpret_cast<const float4*>(Alo + oAj[j]);
        rB0[j] = *reinterpret_cast<const float4*>(Bhi + oBj[j]);
        rB1[j] = *reinterpret_cast<const float4*>(Blo + oBj[j]);
    }

    int nch = K / KC;
    uint32_t ph = 0;
    for (int ch = 0; ch < nch; ch++) {
        if (ch > 0) { mbar_wait(sb + S_MB, ph); ph ^= 1; }
        #pragma unroll
        for (int j = 0; j < 8; j++) {
            *reinterpret_cast<float4*>(smem + S_AH + swoj[j]) = rA0[j];
            *reinterpret_cast<float4*>(smem + S_AL + swoj[j]) = rA1[j];
            *reinterpret_cast<float4*>(smem + S_BH + swoj[j]) = rB0[j];
            *reinterpret_cast<float4*>(smem + S_BL + swoj[j]) = rB1[j];
        }
        fence_async_shared();
        __syncthreads();
        if (wid == 0 && elect1()) {
            #pragma unroll
            for (int ks = 0; ks < 4; ks++) {
                uint64_t off = (uint64_t)(ks * 2);
                mma_bf16_ss(tmem, adh + off, bdh + off, idesc, !(ch == 0 && ks == 0));
                mma_bf16_ss(tmem, adl + off, bdh + off, idesc, true);
                mma_bf16_ss(tmem, adh + off, bdl + off, idesc, true);
            }
            tm_commit(sb + S_MB);
        }
        if (ch + 1 < nch) {
            int k1 = (ch + 1) * KC;
            #pragma unroll
            for (int j = 0; j < 8; j++) {
                rA0[j] = *reinterpret_cast<const float4*>(Ahi + oAj[j] + k1);
                rA1[j] = *reinterpret_cast<const float4*>(Alo + oAj[j] + k1);
                rB0[j] = *reinterpret_cast<const float4*>(Bhi + oBj[j] + k1);
                rB1[j] = *reinterpret_cast<const float4*>(Blo + oBj[j] + k1);
            }
        }
    }
    mbar_wait(sb + S_MB, (uint32_t)((nch - 1) & 1));
    fence_after();

    int m0 = mBase + wid*32;
    float* stg = reinterpret_cast<float*>(smem + S_AH) + wid*(32*33);
    #pragma unroll
    for (int cb = 0; cb < 4; cb++) {
        uint32_t d[32];
        LDTM_X32(d, tmem + cb*32);
        wait_ld();
        int nb = nBase + cb*32;
        #pragma unroll
        for (int c = 0; c < 32; c++) stg[c*33 + lane] = __uint_as_float(d[c]);
        __syncwarp();
        if (EPI == 0) {
            int n = nb + lane;
            #pragma unroll 8
            for (int rr = 0; rr < 32; rr++)
                C[(size_t)(m0+rr)*ldc + n] = stg[lane*33 + rr];
        } else {
            int n = nb + lane;
            float bn = bias[n];
            #pragma unroll 8
            for (int rr = 0; rr < 32; rr++) {
                float t = tanhf(stg[lane*33 + rr] + bn);
                bf16 h, l; bsplit(t, h, l);
                Chi[(size_t)(m0+rr)*ldc + n] = h;
                Clo[(size_t)(m0+rr)*ldc + n] = l;
            }
        }
        __syncwarp();
    }

    __syncthreads();
    if (tid == 0) mbar_inval(sb + S_MB);
    __syncthreads();
    if (wid == 0) tm_dealloc(tmem, 128);

#else  /* SIMT fallback */
    float* As = reinterpret_cast<float*>(smem);
    float* Bs = reinterpret_cast<float*>(smem + 17408);
    const bf16* arh = Ahi + (size_t)(mBase + tid)*lda;
    const bf16* arl = Alo + (size_t)(mBase + tid)*lda;
    const bf16* brh = Bhi + (size_t)(nBase + tid)*ldb;
    const bf16* brl = Blo + (size_t)(nBase + tid)*ldb;
    for (int half = 0; half < 2; half++) {
        float acc[64];
        for (int j = 0; j < 64; j++) acc[j] = 0.f;
        for (int k0 = 0; k0 < K; k0 += 32) {
            for (int q = 0; q < 32; q++) {
                As[tid*33 + q] = brecon(arh[k0+q], arl[k0+q]);
                Bs[tid*33 + q] = brecon(brh[k0+q], brl[k0+q]);
            }
            __syncthreads();
            for (int kk = 0; kk < 32; kk++) {
                float a = As[tid*33 + kk];
                for (int j = 0; j < 64; j++)
                    acc[j] = fmaf(a, Bs[(half*64 + j)*33 + kk], acc[j]);
            }
            __syncthreads();
        }
        int m = mBase + tid;
        int nb = nBase + half*64;
        if (EPI == 0) {
            for (int j = 0; j < 64; j++) C[(size_t)m*ldc + nb + j] = acc[j];
        } else {
            for (int j = 0; j < 64; j++) {
                int n = nb + j;
                float t = tanhf(acc[j] + bias[n]);
                bf16 h, l; bsplit(t, h, l);
                Chi[(size_t)m*ldc + n] = h;
                Clo[(size_t)m*ldc + n] = l;
            }
        }
    }
#endif
}

/* ---------------- output GEMM: one CTA does full N=384 for its M-tile -----
 * A2 streamed once; W_out (7MB) stays L2-hot. TMEM 512 cols (3 D tiles).
 * out[row,n] = sigmoid(acc+bias[n]) * inp[row, 257+n], n < 257.
 */
__global__ __launch_bounds__(256)
void tc_out(const bf16* __restrict__ Ahi, const bf16* __restrict__ Alo,
            const bf16* __restrict__ Bhi, const bf16* __restrict__ Blo,
            const float* __restrict__ bias,
            const float* __restrict__ inp, float* __restrict__ outp)
{
    extern __shared__ char smem[];
    int tid = threadIdx.x;
    int mBase = blockIdx.x * MT;

#ifdef HAS_TCGEN05
    uint32_t sb = smem_u32(smem);
    int wid = tid >> 5, lane = tid & 31;

    if (wid == 0) { tm_alloc(sb + S_TM, 512); tm_relinq(); }
    if (tid == 0) mbar_init(sb + S_MB, 1);
    __syncthreads();
    uint32_t tmem;
    asm volatile("ld.shared.b32 %0, [%1];" : "=r"(tmem) : "r"(sb + S_TM));

    const uint32_t idesc = (1u << 4) | (1u << 7) | (1u << 10)
                         | ((NT / 8) << 17) | ((MT / 16) << 24);
    uint64_t dsc[8];
    #pragma unroll
    for (int p = 0; p < 8; p++) dsc[p] = mk_desc(sb + SO_TILE + p*16384);

    /* plane pointers: 0=AH 1=AL 2=B0H 3=B0L 4=B1H 5=B1L 6=B2H 7=B2L */
    const bf16* pl[8] = { Ahi, Alo,
                          Bhi, Blo,
                          Bhi + (size_t)128*A2K, Blo + (size_t)128*A2K,
                          Bhi + (size_t)256*A2K, Blo + (size_t)256*A2K };

    /* per-thread mapping: idx=j*256+tid, j=0..3; 8 lanes per 128B row */
    int swoj[4]; size_t oA[4], oB[4];
    #pragma unroll
    for (int j = 0; j < 4; j++) {
        int idx = j*256 + tid;
        int r = idx >> 3, c = idx & 7;
        oA[j] = (size_t)(mBase + r)*A2K + c*8;
        oB[j] = (size_t)r*A2K + c*8;
        swoj[j] = (int)(((uint32_t)(r*128 + c*16)) ^ (((uint32_t)(r & 7)) << 4));
    }

    float4 rP[8][4];
    #pragma unroll
    for (int p = 0; p < 8; p++)
        #pragma unroll
        for (int j = 0; j < 4; j++)
            rP[p][j] = *reinterpret_cast<const float4*>(pl[p] + (p < 2 ? oA[j] : oB[j]));

    const int nch = A2K / KC;   /* 72 */
    uint32_t ph = 0;
    for (int ch = 0; ch < nch; ch++) {
        if (ch > 0) { mbar_wait(sb + S_MB, ph); ph ^= 1; }
        #pragma unroll
        for (int p = 0; p < 8; p++)
            #pragma unroll
            for (int j = 0; j < 4; j++)
                *reinterpret_cast<float4*>(smem + SO_TILE + p*16384 + swoj[j]) = rP[p][j];
        fence_async_shared();
        __syncthreads();
        if (wid == 0 && elect1()) {
            #pragma unroll
            for (int ks = 0; ks < 4; ks++) {
                uint64_t off = (uint64_t)(ks * 2);
                #pragma unroll
                for (int nt = 0; nt < 3; nt++) {
                    uint32_t dt = tmem + nt*128;
                    bool first = (ch == 0 && ks == 0);
                    mma_bf16_ss(dt, dsc[0] + off, dsc[2 + 2*nt] + off, idesc, !first);
                    mma_bf16_ss(dt, dsc[1] + off, dsc[2 + 2*nt] + off, idesc, true);
                    mma_bf16_ss(dt, dsc[0] + off, dsc[3 + 2*nt] + off, idesc, true);
                }
            }
            tm_commit(sb + S_MB);
        }
        if (ch + 1 < nch) {
            int k1 = (ch + 1) * KC;
            #pragma unroll
            for (int p = 0; p < 8; p++)
                #pragma unroll
                for (int j = 0; j < 4; j++)
                    rP[p][j] = *reinterpret_cast<const float4*>(pl[p] + (p < 2 ? oA[j] : oB[j]) + k1);
        }
    }
    mbar_wait(sb + S_MB, (uint32_t)((nch - 1) & 1));
    fence_after();

    /* epilogue: warp w -> subpartition s=w&3 rows mBase+32s+lane;
       warps 0-3 handle col-groups 0..5, warps 4-7 handle 6..11 */
    {
        int s = wid & 3, half = wid >> 2;
        int m = mBase + s*32 + lane;
        int b = m & 15, t = m >> 4;
        size_t row = (size_t)b*T_ + t;
        #pragma unroll
        for (int g = 0; g < 6; g++) {
            int cg = half*6 + g;
            int nb = cg*32;
            uint32_t d[32];
            LDTM_X32(d, tmem + nb);
            wait_ld();
            #pragma unroll
            for (int c = 0; c < 32; c++) {
                int n = nb + c;
                if (n < INDIM) {
                    float v = __uint_as_float(d[c]) + bias[n];
                    float sg = 1.f / (1.f + __expf(-v));
                    outp[row*INDIM + n] = sg * inp[row*FEAT + INDIM + n];
                }
            }
        }
    }

    __syncthreads();
    if (tid == 0) mbar_inval(sb + S_MB);
    __syncthreads();
    if (wid == 0) tm_dealloc(tmem, 512);

#else  /* SIMT fallback: slow but correct; never used on sm_103a */
    if (tid < 128) {
        int m = mBase + tid;
        int b = m & 15, t = m >> 4;
        size_t row = (size_t)b*T_ + t;
        for (int n = 0; n < INDIM; n++) {
            float acc = 0.f;
            const bf16* ah = Ahi + (size_t)m*A2K;
            const bf16* al = Alo + (size_t)m*A2K;
            const bf16* bh = Bhi + (size_t)n*A2K;
            const bf16* bl = Blo + (size_t)n*A2K;
            for (int k = 0; k < A2K; k++)
                acc += brecon(ah[k], al[k]) * brecon(bh[k], bl[k]);
            float v = acc + bias[n];
            float sg = 1.f / (1.f + __expf(-v));
            outp[row*INDIM + n] = sg * inp[row*FEAT + INDIM + n];
        }
    }
#endif
}

/* ---------------- SRU scan: bf16 X in, bf16 H out, pipelined ------------- */
#define SUN 8
__global__ void scan_kernel(const float* __restrict__ U,
                            const bf16* __restrict__ Xh, const bf16* __restrict__ Xl,
                            const float* __restrict__ v, const float* __restrict__ bb,
                            bf16* __restrict__ Hh, bf16* __restrict__ Hl)
{
    int idx = blockIdx.x * blockDim.x + threadIdx.x;   // 0..B*H-1
    int b = idx >> 9, h = idx & (H_-1);
    float vf = v[h], vr = v[H_ + h];
    float bf = bb[h], br = bb[H_ + h];
    const float* Ub  = U  + (size_t)b*H3 + h;
    const bf16* Xhb = Xh + (size_t)b*H_ + h;
    const bf16* Xlb = Xl + (size_t)b*H_ + h;
    bf16* Hhb = Hh + (size_t)b*H_ + h;
    bf16* Hlb = Hl + (size_t)b*H_ + h;

    float cxt[SUN], cfp[SUN], crp[SUN], cxn[SUN];
    #pragma unroll
    for (int u = 0; u < SUN; u++) {
        size_t o3 = (size_t)u * (B_*H3);
        size_t o1 = (size_t)u * (B_*H_);
        cxt[u] = Ub[o3]; cfp[u] = Ub[o3 + H_]; crp[u] = Ub[o3 + 2*H_];
        cxn[u] = brecon(Xhb[o1], Xlb[o1]);
    }
    float c = 0.f;
    for (int t0 = 0; t0 < T_; t0 += SUN) {
        float nxt[SUN], nfp[SUN], nrp[SUN], nxn[SUN];
        bool more = (t0 + SUN < T_);
        #pragma unroll
        for (int u = 0; u < SUN; u++) {
            int t = t0 + SUN + u;
            size_t o3 = (size_t)t * (B_*H3);
            size_t o1 = (size_t)t * (B_*H_);
            if (more) {
                nxt[u] = Ub[o3]; nfp[u] = Ub[o3 + H_]; nrp[u] = Ub[o3 + 2*H_];
                nxn[u] = brecon(Xhb[o1], Xlb[o1]);
            } else { nxt[u] = nfp[u] = nrp[u] = nxn[u] = 0.f; }
        }
        #pragma unroll
        for (int u = 0; u < SUN; u++) {
            float f = 1.f / (1.f + __expf(-(fmaf(vf, c, cfp[u]) + bf)));
            float cn = fmaf(f, c - cxt[u], cxt[u]);
            float r = 1.f / (1.f + __expf(-(fmaf(vr, c, crp[u]) + br)));
            float hv = fmaf(r, cn - cxn[u], cxn[u]);
            bf16 hh, hl; bsplit(hv, hh, hl);
            size_t o1 = (size_t)(t0+u) * (B_*H_);
            Hhb[o1] = hh; Hlb[o1] = hl;
            c = cn;
        }
        #pragma unroll
        for (int u = 0; u < SUN; u++) {
            cxt[u] = nxt[u]; cfp[u] = nfp[u]; crp[u] = nrp[u]; cxn[u] = nxn[u];
        }
    }
}

/* ---------------- fused conv6x6 + maxpool3x3 + tanh, bf16 split output --- */
__global__ __launch_bounds__(256)
void convpool_kernel(const float* __restrict__ w, const float* __restrict__ cb,
                     const bf16* __restrict__ inh, const bf16* __restrict__ inl,
                     bf16* __restrict__ A2h, bf16* __restrict__ A2l)
{
    __shared__ float ws[KN][KS][KS];
    __shared__ float bs[KN];
    __shared__ float xin[15][40];
    __shared__ float cv[KN][10][36];
    __shared__ float po[8][32*KN];

    int b  = blockIdx.z;
    int t0 = blockIdx.y * 8;
    int h0 = blockIdx.x * 32;
    int tid = threadIdx.x;

    for (int i = tid; i < KN*KS*KS; i += 256) (&ws[0][0][0])[i] = w[i];
    if (tid < KN) bs[tid] = cb[tid];
    for (int i = tid; i < 15*39; i += 256) {
        int r = i / 39, cc = i % 39;
        int t = t0 - 4 + r, h = h0 - 4 + cc;
        float val = 0.f;
        if (t >= 0 && t < T_ && h >= 0 && h < H_) {
            size_t o = ((size_t)t*B_ + b)*H_ + h;
            val = brecon(inh[o], inl[o]);
        }
        xin[r][cc] = val;
    }
    __syncthreads();

    for (int p = tid; p < 10*34; p += 256) {
        int r = p / 34, cc = p % 34;
        int tt = t0 - 1 + r, hh = h0 - 1 + cc;
        float acc[KN];
        #pragma unroll
        for (int kn = 0; kn < KN; kn++) acc[kn] = 0.f;
        #pragma unroll
        for (int i = 0; i < KS; i++)
            #pragma unroll
            for (int j = 0; j < KS; j++) {
                float x = xin[r + i][cc + j];
                #pragma unroll
                for (int kn = 0; kn < KN; kn++)
                    acc[kn] = fmaf(ws[kn][i][j], x, acc[kn]);
            }
        bool valid = (tt >= 0 && tt < T_ && hh >= 0 && hh < H_);
        #pragma unroll
        for (int kn = 0; kn < KN; kn++)
            cv[kn][r][cc] = valid ? acc[kn] : -3.0e38f;
    }
    __syncthreads();

    {
        int ht = tid & 31, tt = tid >> 5;
        #pragma unroll
        for (int kn = 0; kn < KN; kn++) {
            float m = -3.0e38f;
            #pragma unroll
            for (int dt = 0; dt < 3; dt++)
                #pragma unroll
                for (int dh = 0; dh < 3; dh++)
                    m = fmaxf(m, cv[kn][tt + dt][ht + dh]);
            po[tt][ht*KN + kn] = tanhf(m + bs[kn]);
        }
    }
    __syncthreads();

    for (int i = tid; i < 8*32*KN; i += 256) {
        int row = i / (32*KN), f = i % (32*KN);
        size_t o = ((size_t)(t0 + row)*B_ + b)*A2K + (size_t)h0*KN + f;
        bf16 h, l; bsplit(po[row][f], h, l);
        A2h[o] = h; A2l[o] = l;
    }
}

/* ---------------- driver -------------------------------------------------- */
extern "C" void kernel_launch(void* const* d_in, const int* in_sizes, int n_in,
                              void* d_out, int out_size)
{
    const float* inputs = (const float*)d_in[0];
    const float* W_in   = (const float*)d_in[1];
    const float* b_in   = (const float*)d_in[2];
    const float* W_rnn  = (const float*)d_in[3];
    const float* v_rnn  = (const float*)d_in[4];
    const float* b_rnn  = (const float*)d_in[5];
    const float* conv_k = (const float*)d_in[6];
    const float* conv_b = (const float*)d_in[7];
    const float* W_out  = (const float*)d_in[8];
    const float* b_out  = (const float*)d_in[9];
    float* out = (float*)d_out;

    bf16 *xTh,*xTl,*h0h,*h0l,*h1h,*h1l,*h2h,*h2l,*A2h,*A2l;
    bf16 *Wih,*Wil,*Wr0h,*Wr0l,*Wr1h,*Wr1l,*Woh,*Wol;
    float *U;
    cudaGetSymbolAddress((void**)&xTh, g_xTh); cudaGetSymbolAddress((void**)&xTl, g_xTl);
    cudaGetSymbolAddress((void**)&h0h, g_h0h); cudaGetSymbolAddress((void**)&h0l, g_h0l);
    cudaGetSymbolAddress((void**)&U,   g_U);
    cudaGetSymbolAddress((void**)&h1h, g_h1h); cudaGetSymbolAddress((void**)&h1l, g_h1l);
    cudaGetSymbolAddress((void**)&h2h, g_h2h); cudaGetSymbolAddress((void**)&h2l, g_h2l);
    cudaGetSymbolAddress((void**)&A2h, g_A2h); cudaGetSymbolAddress((void**)&A2l, g_A2l);
    cudaGetSymbolAddress((void**)&Wih, g_Wih); cudaGetSymbolAddress((void**)&Wil, g_Wil);
    cudaGetSymbolAddress((void**)&Wr0h, g_Wr0h); cudaGetSymbolAddress((void**)&Wr0l, g_Wr0l);
    cudaGetSymbolAddress((void**)&Wr1h, g_Wr1h); cudaGetSymbolAddress((void**)&Wr1l, g_Wr1l);
    cudaGetSymbolAddress((void**)&Woh, g_Woh); cudaGetSymbolAddress((void**)&Wol, g_Wol);

    cudaFuncSetAttribute(tc_gemm<0>, cudaFuncAttributeMaxDynamicSharedMemorySize, S_TOT);
    cudaFuncSetAttribute(tc_gemm<1>, cudaFuncAttributeMaxDynamicSharedMemorySize, S_TOT);
    cudaFuncSetAttribute(tc_out, cudaFuncAttributeMaxDynamicSharedMemorySize, SO_TOT);

    // #1 transpose + split input activations
    transpose_kernel<<<M_, 256>>>(inputs, xTh, xTl);
    // #2 fused weight prep (one launch)
    wprep_all<<<3968, 256>>>(W_in, W_rnn, W_out,
                             Wih, Wil, Wr0h, Wr0l, Wr1h, Wr1l, Woh, Wol);

    // #3 input layer GEMM (tanh, split out)  K=832
    tc_gemm<1><<<dim3(512/NT, M_/MT), 128, S_TOT>>>(
        xTh, xTl, KP1, Wih, Wil, KP1,
        nullptr, h0h, h0l, H_, 512, KP1, b_in);

    // #4 SRU layer 0 GEMM, #5 scan
    tc_gemm<0><<<dim3(H3/NT, M_/MT), 128, S_TOT>>>(
        h0h, h0l, H_, Wr0h, Wr0l, H_,
        U, nullptr, nullptr, H3, H3, H_, nullptr);
    scan_kernel<<<(B_*H_)/128, 128>>>(U, h0h, h0l, v_rnn, b_rnn, h1h, h1l);

    // #6 SRU layer 1 GEMM (ncu -s 5 -c 1 captures this launch), #7 scan
    tc_gemm<0><<<dim3(H3/NT, M_/MT), 128, S_TOT>>>(
        h1h, h1l, H_, Wr1h, Wr1l, H_,
        U, nullptr, nullptr, H3, H3, H_, nullptr);
    scan_kernel<<<(B_*H_)/128, 128>>>(U, h1h, h1l, v_rnn + 2*H_, b_rnn + 2*H_, h2h, h2l);

    // #8 fused conv + pool + tanh -> split A2
    convpool_kernel<<<dim3(H_/32, T_/8, B_), 256>>>(conv_k, conv_b, h2h, h2l, A2h, A2l);

    // #9 output GEMM: 125 CTAs, each does full N=384; A2 streamed once
    tc_out<<<M_/MT, 256, SO_TOT>>>(
        A2h, A2l, Woh, Wol, b_out + INDIM, inputs, out);
}